// round 11
// baseline (speedup 1.0000x reference)
#include <cuda_runtime.h>
#include <cstdint>

// Problem constants
#define NSEG 6
#define NCH  512
#define NPOS 16384     // 128*128
#define NBINS 16
#define GEMV_GRID 740  // 148 SMs x 5 blocks (launch_bounds(256,5)) -> all resident

// ---------------- device scratch (no allocation allowed) ----------------
__device__ unsigned g_mbits[NSEG * 512];     // bit-packed mask, 512 u32/segment
__device__ float    g_fm[NSEG * NPOS];       // float 0/1 mask per position
__device__ float    g_ys[NSEG * NCH * NBINS];
__device__ float    g_h1p[4][NSEG * 2048];   // fcA partials (K-split 4)
__device__ float    g_h2p[4][NSEG * 512];    // fcB partials (K-split 4)
__device__ float    g_w0[NSEG * 512];
__device__ float    g_w1[NSEG * 256];
__device__ float    g_w2[NSEG * 128];
__device__ unsigned          g_count;        // barrier arrivals (self-resetting)
__device__ volatile unsigned g_gen;          // barrier generation (monotonic)

// ---------------- K0: mask build (12 blocks x 256 = 3072 threads) --------
__global__ void __launch_bounds__(256) k_mask(const int* __restrict__ parsing)
{
    const int gtid = blockIdx.x * 256 + threadIdx.x;     // 0..3071
    const int s    = gtid >> 9;                           // 0..5
    const int tseg = gtid & 511;                          // 0..511
    const int base = tseg * 32;

    const int4* __restrict__ pv = (const int4*)(parsing + s * 65536);
    const int h  = base >> 7;
    const int w0 = base & 127;

    unsigned mw = 0;
#pragma unroll
    for (int j = 0; j < 32; j += 2) {
        int w = w0 + j;
        int4 v = pv[h * 128 + (w >> 1)];
        unsigned m0 = (v.x != 0), m1 = (v.z != 0);
        mw |= m0 << j;
        mw |= m1 << (j + 1);
    }
    g_mbits[s * 512 + tseg] = mw;

    float4* fmv = (float4*)(g_fm + s * NPOS + base);
#pragma unroll
    for (int q = 0; q < 8; q++) {
        int qq = q << 2;
        float4 f;
        f.x = ((mw >> qq)       & 1u) ? 1.f : 0.f;
        f.y = ((mw >> (qq + 1)) & 1u) ? 1.f : 0.f;
        f.z = ((mw >> (qq + 2)) & 1u) ? 1.f : 0.f;
        f.w = ((mw >> (qq + 3)) & 1u) ? 1.f : 0.f;
        fmv[q] = f;
    }
}

// ---------------- packed f32x2 FMA ----------------
__device__ __forceinline__ void ffma2(unsigned long long& acc,
                                      unsigned long long v,
                                      unsigned long long m)
{
    asm("fma.rn.f32x2 %0, %1, %2, %0;" : "+l"(acc) : "l"(v), "l"(m));
}
#define ULL(f4part) (*(const unsigned long long*)&(f4part))

// ---------------- K1: pool (bins prologue fused), 4 channels / warp ------
// grid = NSEG * 128 blocks, 512 threads = 16 warps (bin each).
__global__ void __launch_bounds__(512, 2) k_pool(const float* __restrict__ xs)
{
    const int bid  = blockIdx.x;          // s*128 + cq
    const int s    = bid >> 7;
    const int cq   = bid & 127;
    const int c0   = cq * 4;
    const int tid  = threadIdx.x;
    const int warp = tid >> 5;
    const int lane = tid & 31;

    // --- bins prologue: recompute windows from g_mbits (L2-hot, 2KB) ---
    __shared__ int ssum[512];
    __shared__ int sst[NBINS], sen[NBINS];
    __shared__ int sA[NBINS], sB[NBINS];
    __shared__ float srd[NBINS];

    const unsigned mw = g_mbits[s * 512 + tid];
    const int cnt = __popc(mw);
    const int base = tid * 32;

    ssum[tid] = cnt;
    __syncthreads();
    for (int off = 1; off < 512; off <<= 1) {
        int v = (tid >= off) ? ssum[tid - off] : 0;
        __syncthreads();
        ssum[tid] += v;
        __syncthreads();
    }
    const int incl = ssum[tid];
    const int L    = ssum[511];
    const int exc  = incl - cnt;

    if (tid < NBINS) {
        int k  = tid;
        int st = (k * L) >> 4;
        int en = ((k + 1) * L + 15) >> 4;
        sst[k] = st;
        sen[k] = en;
        int d = en - st; if (d < 1) d = 1;
        srd[k] = 1.0f / (float)d;
        sA[k] = 0;
        sB[k] = 0;
    }
    __syncthreads();

    {
        int r = exc;
#pragma unroll 1
        for (int j = 0; j < 32; j++) {
            if ((mw >> j) & 1u) {
                int p = base + j;
                for (int k = 0; k < NBINS; k++) {
                    if (r == sst[k])     sA[k] = p;
                    if (r + 1 == sen[k]) sB[k] = p + 1;
                }
                r++;
            }
        }
    }
    __syncthreads();

    const int lo = sA[warp];
    const int hi = sB[warp];

    // --- pooling: 4 channels per warp, fm-weighted FFMA2 ---
    const size_t chbase = ((size_t)(s * NCH + c0)) << 14;
    const float4* __restrict__ xa4 = (const float4*)(xs + chbase);
    const float4* __restrict__ xb4 = xa4 + (NPOS >> 2);
    const float4* __restrict__ xc4 = xb4 + (NPOS >> 2);
    const float4* __restrict__ xd4 = xc4 + (NPOS >> 2);
    const float4* __restrict__ fm4 = (const float4*)(g_fm + s * NPOS);

    const int ilo2 = (lo + 3) >> 2;
    const int ihi2 = hi >> 2;

    unsigned long long accA = 0, accB = 0, accC = 0, accD = 0;
    float eA = 0.f, eB = 0.f, eC = 0.f, eD = 0.f;

    for (int i = ilo2 + lane; i < ihi2; i += 32) {
        float4 f0 = fm4[i];
        float4 a0 = xa4[i];
        float4 b0 = xb4[i];
        float4 c0v = xc4[i];
        float4 d0 = xd4[i];
        ffma2(accA, ULL(a0.x), ULL(f0.x));
        ffma2(accA, ULL(a0.z), ULL(f0.z));
        ffma2(accB, ULL(b0.x), ULL(f0.x));
        ffma2(accB, ULL(b0.z), ULL(f0.z));
        ffma2(accC, ULL(c0v.x), ULL(f0.x));
        ffma2(accC, ULL(c0v.z), ULL(f0.z));
        ffma2(accD, ULL(d0.x), ULL(f0.x));
        ffma2(accD, ULL(d0.z), ULL(f0.z));
    }

    if (lane == 0) {
        for (int e = (lo >> 2); e < ilo2; e++) {
            float4 fa = fm4[e];
            float4 va = xa4[e];
            float4 vb = xb4[e];
            float4 vc = xc4[e];
            float4 vd = xd4[e];
            int p = e << 2;
            float m0 = (p     >= lo && p     < hi) ? fa.x : 0.f;
            float m1 = (p + 1 >= lo && p + 1 < hi) ? fa.y : 0.f;
            float m2 = (p + 2 >= lo && p + 2 < hi) ? fa.z : 0.f;
            float m3 = (p + 3 >= lo && p + 3 < hi) ? fa.w : 0.f;
            eA += va.x * m0 + va.y * m1 + va.z * m2 + va.w * m3;
            eB += vb.x * m0 + vb.y * m1 + vb.z * m2 + vb.w * m3;
            eC += vc.x * m0 + vc.y * m1 + vc.z * m2 + vc.w * m3;
            eD += vd.x * m0 + vd.y * m1 + vd.z * m2 + vd.w * m3;
        }
    }
    if (lane == 1) {
        int e0 = (ihi2 > ilo2) ? ihi2 : ilo2;
        for (int e = e0; e < ((hi + 3) >> 2); e++) {
            float4 fa = fm4[e];
            float4 va = xa4[e];
            float4 vb = xb4[e];
            float4 vc = xc4[e];
            float4 vd = xd4[e];
            int p = e << 2;
            float m0 = (p     >= lo && p     < hi) ? fa.x : 0.f;
            float m1 = (p + 1 >= lo && p + 1 < hi) ? fa.y : 0.f;
            float m2 = (p + 2 >= lo && p + 2 < hi) ? fa.z : 0.f;
            float m3 = (p + 3 >= lo && p + 3 < hi) ? fa.w : 0.f;
            eA += va.x * m0 + va.y * m1 + va.z * m2 + va.w * m3;
            eB += vb.x * m0 + vb.y * m1 + vb.z * m2 + vb.w * m3;
            eC += vc.x * m0 + vc.y * m1 + vc.z * m2 + vc.w * m3;
            eD += vd.x * m0 + vd.y * m1 + vd.z * m2 + vd.w * m3;
        }
    }

    float2 a2 = *(float2*)&accA;
    float2 b2 = *(float2*)&accB;
    float2 c2 = *(float2*)&accC;
    float2 d2 = *(float2*)&accD;
    float rA = a2.x + a2.y + eA;
    float rB = b2.x + b2.y + eB;
    float rC = c2.x + c2.y + eC;
    float rD = d2.x + d2.y + eD;
#pragma unroll
    for (int o = 16; o; o >>= 1) {
        rA += __shfl_xor_sync(0xffffffffu, rA, o);
        rB += __shfl_xor_sync(0xffffffffu, rB, o);
        rC += __shfl_xor_sync(0xffffffffu, rC, o);
        rD += __shfl_xor_sync(0xffffffffu, rD, o);
    }
    if (lane == 0) {
        float rd = srd[warp];
        float* yb = g_ys + s * (NCH * NBINS) + c0 * NBINS + warp;
        yb[0]         = rA * rd;
        yb[NBINS]     = rB * rd;
        yb[2 * NBINS] = rC * rd;
        yb[3 * NBINS] = rD * rd;
    }
}

// ---------------- helpers ----------------
__device__ __forceinline__ float dot4(float4 a, float4 b, float acc)
{
    acc = fmaf(a.x, b.x, acc);
    acc = fmaf(a.y, b.y, acc);
    acc = fmaf(a.z, b.z, acc);
    acc = fmaf(a.w, b.w, acc);
    return acc;
}
__device__ __forceinline__ float4 add4(float4 a, float4 b)
{ return make_float4(a.x + b.x, a.y + b.y, a.z + b.z, a.w + b.w); }

__device__ __forceinline__ float warp_red(float a)
{
#pragma unroll
    for (int o = 16; o; o >>= 1) a += __shfl_xor_sync(0xffffffffu, a, o);
    return a;
}

// Grid-wide barrier: all blocks resident (guaranteed by launch_bounds + grid).
__device__ __forceinline__ void grid_barrier()
{
    __syncthreads();
    __threadfence();
    if (threadIdx.x == 0) {
        unsigned gen = g_gen;
        if (atomicAdd(&g_count, 1u) == gridDim.x - 1) {
            g_count = 0;
            __threadfence();
            g_gen = gen + 1;            // release
        } else {
            int backoff = 32;
            while (g_gen == gen) {
                __nanosleep(backoff);
                if (backoff < 256) backoff <<= 1;
            }
        }
        __threadfence();                // acquire
    }
    __syncthreads();
}

// ---------------- fcA: 2048x8192 GEMV, K-split 4 (standalone, proven) ----
__global__ void __launch_bounds__(256) k_fcA(const float* __restrict__ W)
{
    __shared__ float4 sx[512];                // 2048-float chunk of ys
    const int bid   = blockIdx.x;
    const int s     = bid >> 10;
    const int rem   = bid & 1023;
    const int chunk = rem >> 8;
    const int row   = (rem & 255) * 8 + (threadIdx.x >> 5);
    const int lane  = threadIdx.x & 31;

    const float4* __restrict__ xv = (const float4*)(g_ys + s * 8192 + chunk * 2048);
    for (int i = threadIdx.x; i < 512; i += 256) sx[i] = xv[i];
    __syncthreads();

    const float4* __restrict__ wv =
        (const float4*)(W + (size_t)(s * 2048 + row) * 8192 + chunk * 2048);

    float a0 = 0.f, a1 = 0.f, a2 = 0.f, a3 = 0.f;
#pragma unroll 2
    for (int t = 0; t < 4; t++) {
        const int b = t * 128 + lane;
        float4 w0 = wv[b], w1 = wv[b + 32], w2 = wv[b + 64], w3 = wv[b + 96];
        a0 = dot4(w0, sx[b], a0);
        a1 = dot4(w1, sx[b + 32], a1);
        a2 = dot4(w2, sx[b + 64], a2);
        a3 = dot4(w3, sx[b + 96], a3);
    }
    float a = warp_red((a0 + a1) + (a2 + a3));
    if (lane == 0) g_h1p[chunk][s * 2048 + row] = a;
}

// ---------------- fused fcB (Ksplit4) -> fcC -> p1 -> p2 -> p3 ----------
// 740 persistent blocks x 256 threads; 4 grid barriers.
__global__ void __launch_bounds__(256, 5) k_fcBCT(
    const float* __restrict__ fcB_w, const float* __restrict__ bA,
    const float* __restrict__ fcC_w, const float* __restrict__ bB,
    const float* __restrict__ bC,
    const float* __restrict__ p1w, const float* __restrict__ p1b,
    const float* __restrict__ p2w, const float* __restrict__ p2b,
    const float* __restrict__ p3w, const float* __restrict__ p3b,
    float* __restrict__ out)
{
    __shared__ float4 sx[128];                // 512-float stage (max for any phase)
    const int tid  = threadIdx.x;
    const int wid  = tid >> 5;
    const int lane = tid & 31;

    // ---- phase fcB: 1536 tiles (6 seg x 4 chunks x 64 rowblocks), K-chunk 512
    for (int t = blockIdx.x; t < 1536; t += gridDim.x) {
        const int s     = t >> 8;
        const int rem   = t & 255;
        const int chunk = rem >> 6;
        const int row   = (rem & 63) * 8 + wid;

        __syncthreads();
        const int xoff = (s * 2048 + chunk * 512) >> 2;
        if (tid < 128) {
            const float4* q0 = ((const float4*)g_h1p[0]) + xoff;
            const float4* q1 = ((const float4*)g_h1p[1]) + xoff;
            const float4* q2 = ((const float4*)g_h1p[2]) + xoff;
            const float4* q3 = ((const float4*)g_h1p[3]) + xoff;
            const float4* bb = ((const float4*)bA) + xoff;
            sx[tid] = add4(add4(add4(q0[tid], q1[tid]), add4(q2[tid], q3[tid])), bb[tid]);
        }
        __syncthreads();

        const float4* __restrict__ wv =
            (const float4*)(fcB_w + (size_t)(s * 512 + row) * 2048 + chunk * 512);
        float a0 = dot4(wv[lane],      sx[lane],      0.f);
        float a1 = dot4(wv[lane + 32], sx[lane + 32], 0.f);
        float a2 = dot4(wv[lane + 64], sx[lane + 64], 0.f);
        float a3 = dot4(wv[lane + 96], sx[lane + 96], 0.f);
        float a = warp_red((a0 + a1) + (a2 + a3));
        if (lane == 0) g_h2p[chunk][s * 512 + row] = a;
    }
    grid_barrier();

    // ---- phase fcC: 384 tiles (6 seg x 64 rowblocks), K=512
    for (int t = blockIdx.x; t < 384; t += gridDim.x) {
        const int s   = t >> 6;
        const int row = (t & 63) * 8 + wid;

        __syncthreads();
        const int xoff = (s * 512) >> 2;
        if (tid < 128) {
            const float4* q0 = ((const float4*)g_h2p[0]) + xoff;
            const float4* q1 = ((const float4*)g_h2p[1]) + xoff;
            const float4* q2 = ((const float4*)g_h2p[2]) + xoff;
            const float4* q3 = ((const float4*)g_h2p[3]) + xoff;
            const float4* bb = ((const float4*)bB) + xoff;
            sx[tid] = add4(add4(add4(q0[tid], q1[tid]), add4(q2[tid], q3[tid])), bb[tid]);
        }
        __syncthreads();

        const float4* __restrict__ wv = (const float4*)(fcC_w + (size_t)(s * 512 + row) * 512);
        float a0 = dot4(wv[lane],      sx[lane],      0.f);
        float a1 = dot4(wv[lane + 32], sx[lane + 32], 0.f);
        float a2 = dot4(wv[lane + 64], sx[lane + 64], 0.f);
        float a3 = dot4(wv[lane + 96], sx[lane + 96], 0.f);
        float a = warp_red((a0 + a1) + (a2 + a3));
        if (lane == 0) {
            float r = a + bC[s * 512 + row];
            g_w0[s * 512 + row] = r;
            out[s * 960 + row]  = r;
        }
    }
    grid_barrier();

    // ---- phase p1: 192 tiles (6 seg x 32 rowblocks), 256 rows, K=512
    for (int t = blockIdx.x; t < 192; t += gridDim.x) {
        const int s   = t >> 5;
        const int row = (t & 31) * 8 + wid;

        __syncthreads();
        if (tid < 128) sx[tid] = ((const float4*)(g_w0 + s * 512))[tid];
        __syncthreads();

        const float4* __restrict__ wv = (const float4*)(p1w + (size_t)row * 512);
        float a0 = dot4(wv[lane],      sx[lane],      0.f);
        float a1 = dot4(wv[lane + 32], sx[lane + 32], 0.f);
        float a2 = dot4(wv[lane + 64], sx[lane + 64], 0.f);
        float a3 = dot4(wv[lane + 96], sx[lane + 96], 0.f);
        float a = warp_red((a0 + a1) + (a2 + a3));
        if (lane == 0) {
            float r = a + p1b[row];
            g_w1[s * 256 + row] = r;
            out[s * 960 + 512 + row] = r;
        }
    }
    grid_barrier();

    // ---- phase p2: 96 tiles (6 seg x 16 rowblocks), 128 rows, K=256
    for (int t = blockIdx.x; t < 96; t += gridDim.x) {
        const int s   = t >> 4;
        const int row = (t & 15) * 8 + wid;

        __syncthreads();
        if (tid < 64) sx[tid] = ((const float4*)(g_w1 + s * 256))[tid];
        __syncthreads();

        const float4* __restrict__ wv = (const float4*)(p2w + (size_t)row * 256);
        float a0 = dot4(wv[lane],      sx[lane],      0.f);
        float a1 = dot4(wv[lane + 32], sx[lane + 32], 0.f);
        float a = warp_red(a0 + a1);
        if (lane == 0) {
            float r = a + p2b[row];
            g_w2[s * 128 + row] = r;
            out[s * 960 + 768 + row] = r;
        }
    }
    grid_barrier();

    // ---- phase p3: 48 tiles (6 seg x 8 rowblocks), 64 rows, K=128
    for (int t = blockIdx.x; t < 48; t += gridDim.x) {
        const int s   = t >> 3;
        const int row = (t & 7) * 8 + wid;

        __syncthreads();
        if (tid < 32) sx[tid] = ((const float4*)(g_w2 + s * 128))[tid];
        __syncthreads();

        const float4* __restrict__ wv = (const float4*)(p3w + (size_t)row * 128);
        float a = warp_red(dot4(wv[lane], sx[lane], 0.f));
        if (lane == 0) out[s * 960 + 896 + row] = a + p3b[row];
    }
}

// ---------------- launch ----------------
extern "C" void kernel_launch(void* const* d_in, const int* in_sizes, int n_in,
                              void* d_out, int out_size)
{
    const float* xs      = (const float*)d_in[0];
    const int*   parsing = (const int*)  d_in[1];
    const float* fcA_w   = (const float*)d_in[2];
    const float* fcA_b   = (const float*)d_in[3];
    const float* fcB_w   = (const float*)d_in[4];
    const float* fcB_b   = (const float*)d_in[5];
    const float* fcC_w   = (const float*)d_in[6];
    const float* fcC_b   = (const float*)d_in[7];
    const float* p1_w    = (const float*)d_in[8];
    const float* p1_b    = (const float*)d_in[9];
    const float* p2_w    = (const float*)d_in[10];
    const float* p2_b    = (const float*)d_in[11];
    const float* p3_w    = (const float*)d_in[12];
    const float* p3_b    = (const float*)d_in[13];
    float* out = (float*)d_out;

    k_mask<<<12, 256>>>(parsing);                    // #0
    k_pool<<<NSEG * 128, 512>>>(xs);                 // #1
    k_fcA <<<NSEG * 256 * 4, 256>>>(fcA_w);          // #2
    k_fcBCT<<<GEMV_GRID, 256>>>(fcB_w, fcA_b, fcC_w, fcB_b, fcC_b,
                                p1_w, p1_b, p2_w, p2_b, p3_w, p3_b, out);  // #3 <- profiled
}

// round 12
// speedup vs baseline: 1.2042x; 1.2042x over previous
#include <cuda_runtime.h>
#include <cstdint>

// Problem constants
#define NSEG 6
#define NCH  512
#define NPOS 16384     // 128*128
#define NBINS 16
#define GEMV_GRID 740  // 148 SMs x 5 blocks (launch_bounds(256,5)) -> all resident

// ---------------- device scratch (no allocation allowed) ----------------
__device__ unsigned g_mbits[NSEG * 512];     // bit-packed mask, 512 u32/segment
__device__ float    g_fm[NSEG * NPOS];       // float 0/1 mask per position
__device__ int      g_posA[NSEG * NBINS];    // bin window start (position)
__device__ int      g_posB[NSEG * NBINS];    // bin window end (exclusive)
__device__ float    g_rdenom[NSEG * NBINS];  // 1/denom per bin
__device__ float    g_ys[NSEG * NCH * NBINS];
__device__ float    g_h1p[4][NSEG * 2048];   // fcA partials (K-split 4)
__device__ float    g_h2p[4][NSEG * 512];    // fcB partials (K-split 4)
__device__ float    g_w0[NSEG * 512];
__device__ float    g_w1[NSEG * 256];
__device__ float    g_w2[NSEG * 128];
__device__ unsigned          g_count;        // barrier arrivals (self-resetting)
__device__ volatile unsigned g_gen;          // barrier generation (monotonic)

// ---------------- K0: prep = mask + fm + scan + bin boundaries ----------
// grid = 6 blocks (one per segment), 512 threads, 32 positions/thread.
__global__ void __launch_bounds__(512) k_prep(const int* __restrict__ parsing)
{
    const int s = blockIdx.x;
    const int tid = threadIdx.x;
    __shared__ int ssum[512];
    __shared__ int sstart[NBINS], send[NBINS];

    const int4* __restrict__ pv = (const int4*)(parsing + s * 65536); // [256,256]
    const int base = tid * 32;   // 32 consecutive positions, same h row

    int cnt = 0;
    unsigned mw = 0;
    const int h = base >> 7;
    const int w0 = base & 127;
#pragma unroll
    for (int j = 0; j < 32; j += 2) {
        int w = w0 + j;
        int4 v = pv[h * 128 + (w >> 1)];
        int m0 = (v.x != 0);
        int m1 = (v.z != 0);
        cnt += m0 + m1;
        mw |= ((unsigned)m0) << j;
        mw |= ((unsigned)m1) << (j + 1);
    }
    g_mbits[s * 512 + tid] = mw;

    // float 0/1 mask, 8 float4 stores (128B contiguous per thread)
    {
        float4* fmv = (float4*)(g_fm + s * NPOS + base);
#pragma unroll
        for (int q = 0; q < 8; q++) {
            int qq = q << 2;
            float4 f;
            f.x = ((mw >> qq)       & 1u) ? 1.f : 0.f;
            f.y = ((mw >> (qq + 1)) & 1u) ? 1.f : 0.f;
            f.z = ((mw >> (qq + 2)) & 1u) ? 1.f : 0.f;
            f.w = ((mw >> (qq + 3)) & 1u) ? 1.f : 0.f;
            fmv[q] = f;
        }
    }

    ssum[tid] = cnt;
    __syncthreads();
    for (int off = 1; off < 512; off <<= 1) {
        int v = (tid >= off) ? ssum[tid - off] : 0;
        __syncthreads();
        ssum[tid] += v;
        __syncthreads();
    }
    const int incl = ssum[tid];
    const int L    = ssum[511];
    const int exc  = incl - cnt;

    if (tid < NBINS) {
        int k  = tid;
        int st = (k * L) >> 4;
        int en = ((k + 1) * L + 15) >> 4;
        sstart[k] = st;
        send[k]   = en;
        int d = en - st; if (d < 1) d = 1;
        g_rdenom[s * NBINS + k] = 1.0f / (float)d;
        g_posA[s * NBINS + k] = 0;
        g_posB[s * NBINS + k] = 0;
    }
    __syncthreads();

    int r = exc;
#pragma unroll 1
    for (int j = 0; j < 32; j++) {
        if ((mw >> j) & 1u) {
            int p = base + j;
            for (int k = 0; k < NBINS; k++) {
                if (r == sstart[k])   g_posA[s * NBINS + k] = p;
                if (r + 1 == send[k]) g_posB[s * NBINS + k] = p + 1;
            }
            r++;
        }
    }
}

// ---------------- packed f32x2 FMA ----------------
__device__ __forceinline__ void ffma2(unsigned long long& acc,
                                      unsigned long long v,
                                      unsigned long long m)
{
    asm("fma.rn.f32x2 %0, %1, %2, %0;" : "+l"(acc) : "l"(v), "l"(m));
}
#define ULL(f4part) (*(const unsigned long long*)&(f4part))

// ---------------- K1: masked adaptive pool, 4 channels / warp ------------
// grid = NSEG * 128 blocks (channel quads), 512 threads = 16 warps (bin each).
__global__ void __launch_bounds__(512, 2) k_pool(const float* __restrict__ xs)
{
    const int bid  = blockIdx.x;          // s*128 + cq
    const int s    = bid >> 7;
    const int cq   = bid & 127;
    const int c0   = cq * 4;
    const int warp = threadIdx.x >> 5;
    const int lane = threadIdx.x & 31;

    const int lo = g_posA[s * NBINS + warp];
    const int hi = g_posB[s * NBINS + warp];

    const size_t chbase = ((size_t)(s * NCH + c0)) << 14;
    const float4* __restrict__ xa4 = (const float4*)(xs + chbase);
    const float4* __restrict__ xb4 = xa4 + (NPOS >> 2);
    const float4* __restrict__ xc4 = xb4 + (NPOS >> 2);
    const float4* __restrict__ xd4 = xc4 + (NPOS >> 2);
    const float4* __restrict__ fm4 = (const float4*)(g_fm + s * NPOS);

    const int ilo2 = (lo + 3) >> 2;       // first fully-inside float4
    const int ihi2 = hi >> 2;             // end of fully-inside float4s

    unsigned long long accA = 0, accB = 0, accC = 0, accD = 0;
    float eA = 0.f, eB = 0.f, eC = 0.f, eD = 0.f;

    for (int i = ilo2 + lane; i < ihi2; i += 32) {
        float4 f0 = fm4[i];
        float4 a0 = xa4[i];
        float4 b0 = xb4[i];
        float4 c0v = xc4[i];
        float4 d0 = xd4[i];
        ffma2(accA, ULL(a0.x), ULL(f0.x));
        ffma2(accA, ULL(a0.z), ULL(f0.z));
        ffma2(accB, ULL(b0.x), ULL(f0.x));
        ffma2(accB, ULL(b0.z), ULL(f0.z));
        ffma2(accC, ULL(c0v.x), ULL(f0.x));
        ffma2(accC, ULL(c0v.z), ULL(f0.z));
        ffma2(accD, ULL(d0.x), ULL(f0.x));
        ffma2(accD, ULL(d0.z), ULL(f0.z));
    }

    // edge float4s (≤1 each side) with explicit window checks
    if (lane == 0) {
        for (int e = (lo >> 2); e < ilo2; e++) {
            float4 fa = fm4[e];
            float4 va = xa4[e];
            float4 vb = xb4[e];
            float4 vc = xc4[e];
            float4 vd = xd4[e];
            int p = e << 2;
            float m0 = (p     >= lo && p     < hi) ? fa.x : 0.f;
            float m1 = (p + 1 >= lo && p + 1 < hi) ? fa.y : 0.f;
            float m2 = (p + 2 >= lo && p + 2 < hi) ? fa.z : 0.f;
            float m3 = (p + 3 >= lo && p + 3 < hi) ? fa.w : 0.f;
            eA += va.x * m0 + va.y * m1 + va.z * m2 + va.w * m3;
            eB += vb.x * m0 + vb.y * m1 + vb.z * m2 + vb.w * m3;
            eC += vc.x * m0 + vc.y * m1 + vc.z * m2 + vc.w * m3;
            eD += vd.x * m0 + vd.y * m1 + vd.z * m2 + vd.w * m3;
        }
    }
    if (lane == 1) {
        int e0 = (ihi2 > ilo2) ? ihi2 : ilo2;
        for (int e = e0; e < ((hi + 3) >> 2); e++) {
            float4 fa = fm4[e];
            float4 va = xa4[e];
            float4 vb = xb4[e];
            float4 vc = xc4[e];
            float4 vd = xd4[e];
            int p = e << 2;
            float m0 = (p     >= lo && p     < hi) ? fa.x : 0.f;
            float m1 = (p + 1 >= lo && p + 1 < hi) ? fa.y : 0.f;
            float m2 = (p + 2 >= lo && p + 2 < hi) ? fa.z : 0.f;
            float m3 = (p + 3 >= lo && p + 3 < hi) ? fa.w : 0.f;
            eA += va.x * m0 + va.y * m1 + va.z * m2 + va.w * m3;
            eB += vb.x * m0 + vb.y * m1 + vb.z * m2 + vb.w * m3;
            eC += vc.x * m0 + vc.y * m1 + vc.z * m2 + vc.w * m3;
            eD += vd.x * m0 + vd.y * m1 + vd.z * m2 + vd.w * m3;
        }
    }

    float2 a2 = *(float2*)&accA;
    float2 b2 = *(float2*)&accB;
    float2 c2 = *(float2*)&accC;
    float2 d2 = *(float2*)&accD;
    float rA = a2.x + a2.y + eA;
    float rB = b2.x + b2.y + eB;
    float rC = c2.x + c2.y + eC;
    float rD = d2.x + d2.y + eD;
#pragma unroll
    for (int o = 16; o; o >>= 1) {
        rA += __shfl_xor_sync(0xffffffffu, rA, o);
        rB += __shfl_xor_sync(0xffffffffu, rB, o);
        rC += __shfl_xor_sync(0xffffffffu, rC, o);
        rD += __shfl_xor_sync(0xffffffffu, rD, o);
    }
    if (lane == 0) {
        float rd = g_rdenom[s * NBINS + warp];
        float* yb = g_ys + s * (NCH * NBINS) + c0 * NBINS + warp;
        yb[0]         = rA * rd;
        yb[NBINS]     = rB * rd;
        yb[2 * NBINS] = rC * rd;
        yb[3 * NBINS] = rD * rd;
    }
}

// ---------------- helpers ----------------
__device__ __forceinline__ float dot4(float4 a, float4 b, float acc)
{
    acc = fmaf(a.x, b.x, acc);
    acc = fmaf(a.y, b.y, acc);
    acc = fmaf(a.z, b.z, acc);
    acc = fmaf(a.w, b.w, acc);
    return acc;
}
__device__ __forceinline__ float4 add4(float4 a, float4 b)
{ return make_float4(a.x + b.x, a.y + b.y, a.z + b.z, a.w + b.w); }

__device__ __forceinline__ float warp_red(float a)
{
#pragma unroll
    for (int o = 16; o; o >>= 1) a += __shfl_xor_sync(0xffffffffu, a, o);
    return a;
}

// Grid-wide barrier: all blocks resident (guaranteed by launch_bounds + grid).
__device__ __forceinline__ void grid_barrier()
{
    __syncthreads();
    __threadfence();
    if (threadIdx.x == 0) {
        unsigned gen = g_gen;
        if (atomicAdd(&g_count, 1u) == gridDim.x - 1) {
            g_count = 0;
            __threadfence();
            g_gen = gen + 1;            // release
        } else {
            int backoff = 32;
            while (g_gen == gen) {
                __nanosleep(backoff);
                if (backoff < 256) backoff <<= 1;
            }
        }
        __threadfence();                // acquire
    }
    __syncthreads();
}

// ---------------- fcA: 2048x8192 GEMV, K-split 4 (standalone, proven) ----
__global__ void __launch_bounds__(256) k_fcA(const float* __restrict__ W)
{
    __shared__ float4 sx[512];                // 2048-float chunk of ys
    const int bid   = blockIdx.x;
    const int s     = bid >> 10;
    const int rem   = bid & 1023;
    const int chunk = rem >> 8;
    const int row   = (rem & 255) * 8 + (threadIdx.x >> 5);
    const int lane  = threadIdx.x & 31;

    const float4* __restrict__ xv = (const float4*)(g_ys + s * 8192 + chunk * 2048);
    for (int i = threadIdx.x; i < 512; i += 256) sx[i] = xv[i];
    __syncthreads();

    const float4* __restrict__ wv =
        (const float4*)(W + (size_t)(s * 2048 + row) * 8192 + chunk * 2048);

    float a0 = 0.f, a1 = 0.f, a2 = 0.f, a3 = 0.f;
#pragma unroll 2
    for (int t = 0; t < 4; t++) {
        const int b = t * 128 + lane;
        float4 w0 = wv[b], w1 = wv[b + 32], w2 = wv[b + 64], w3 = wv[b + 96];
        a0 = dot4(w0, sx[b], a0);
        a1 = dot4(w1, sx[b + 32], a1);
        a2 = dot4(w2, sx[b + 64], a2);
        a3 = dot4(w3, sx[b + 96], a3);
    }
    float a = warp_red((a0 + a1) + (a2 + a3));
    if (lane == 0) g_h1p[chunk][s * 2048 + row] = a;
}

// ---------------- fused fcB (Ksplit4) -> fcC -> p1 -> p2 -> p3 ----------
// 740 persistent blocks x 256 threads; 4 grid barriers.
__global__ void __launch_bounds__(256, 5) k_fcBCT(
    const float* __restrict__ fcB_w, const float* __restrict__ bA,
    const float* __restrict__ fcC_w, const float* __restrict__ bB,
    const float* __restrict__ bC,
    const float* __restrict__ p1w, const float* __restrict__ p1b,
    const float* __restrict__ p2w, const float* __restrict__ p2b,
    const float* __restrict__ p3w, const float* __restrict__ p3b,
    float* __restrict__ out)
{
    __shared__ float4 sx[128];                // 512-float stage (max for any phase)
    const int tid  = threadIdx.x;
    const int wid  = tid >> 5;
    const int lane = tid & 31;

    // ---- phase fcB: 1536 tiles (6 seg x 4 chunks x 64 rowblocks), K-chunk 512
    for (int t = blockIdx.x; t < 1536; t += gridDim.x) {
        const int s     = t >> 8;
        const int rem   = t & 255;
        const int chunk = rem >> 6;
        const int row   = (rem & 63) * 8 + wid;

        __syncthreads();
        const int xoff = (s * 2048 + chunk * 512) >> 2;
        if (tid < 128) {
            const float4* q0 = ((const float4*)g_h1p[0]) + xoff;
            const float4* q1 = ((const float4*)g_h1p[1]) + xoff;
            const float4* q2 = ((const float4*)g_h1p[2]) + xoff;
            const float4* q3 = ((const float4*)g_h1p[3]) + xoff;
            const float4* bb = ((const float4*)bA) + xoff;
            sx[tid] = add4(add4(add4(q0[tid], q1[tid]), add4(q2[tid], q3[tid])), bb[tid]);
        }
        __syncthreads();

        const float4* __restrict__ wv =
            (const float4*)(fcB_w + (size_t)(s * 512 + row) * 2048 + chunk * 512);
        float a0 = dot4(wv[lane],      sx[lane],      0.f);
        float a1 = dot4(wv[lane + 32], sx[lane + 32], 0.f);
        float a2 = dot4(wv[lane + 64], sx[lane + 64], 0.f);
        float a3 = dot4(wv[lane + 96], sx[lane + 96], 0.f);
        float a = warp_red((a0 + a1) + (a2 + a3));
        if (lane == 0) g_h2p[chunk][s * 512 + row] = a;
    }
    grid_barrier();

    // ---- phase fcC: 384 tiles (6 seg x 64 rowblocks), K=512
    for (int t = blockIdx.x; t < 384; t += gridDim.x) {
        const int s   = t >> 6;
        const int row = (t & 63) * 8 + wid;

        __syncthreads();
        const int xoff = (s * 512) >> 2;
        if (tid < 128) {
            const float4* q0 = ((const float4*)g_h2p[0]) + xoff;
            const float4* q1 = ((const float4*)g_h2p[1]) + xoff;
            const float4* q2 = ((const float4*)g_h2p[2]) + xoff;
            const float4* q3 = ((const float4*)g_h2p[3]) + xoff;
            const float4* bb = ((const float4*)bB) + xoff;
            sx[tid] = add4(add4(add4(q0[tid], q1[tid]), add4(q2[tid], q3[tid])), bb[tid]);
        }
        __syncthreads();

        const float4* __restrict__ wv = (const float4*)(fcC_w + (size_t)(s * 512 + row) * 512);
        float a0 = dot4(wv[lane],      sx[lane],      0.f);
        float a1 = dot4(wv[lane + 32], sx[lane + 32], 0.f);
        float a2 = dot4(wv[lane + 64], sx[lane + 64], 0.f);
        float a3 = dot4(wv[lane + 96], sx[lane + 96], 0.f);
        float a = warp_red((a0 + a1) + (a2 + a3));
        if (lane == 0) {
            float r = a + bC[s * 512 + row];
            g_w0[s * 512 + row] = r;
            out[s * 960 + row]  = r;
        }
    }
    grid_barrier();

    // ---- phase p1: 192 tiles (6 seg x 32 rowblocks), 256 rows, K=512
    for (int t = blockIdx.x; t < 192; t += gridDim.x) {
        const int s   = t >> 5;
        const int row = (t & 31) * 8 + wid;

        __syncthreads();
        if (tid < 128) sx[tid] = ((const float4*)(g_w0 + s * 512))[tid];
        __syncthreads();

        const float4* __restrict__ wv = (const float4*)(p1w + (size_t)row * 512);
        float a0 = dot4(wv[lane],      sx[lane],      0.f);
        float a1 = dot4(wv[lane + 32], sx[lane + 32], 0.f);
        float a2 = dot4(wv[lane + 64], sx[lane + 64], 0.f);
        float a3 = dot4(wv[lane + 96], sx[lane + 96], 0.f);
        float a = warp_red((a0 + a1) + (a2 + a3));
        if (lane == 0) {
            float r = a + p1b[row];
            g_w1[s * 256 + row] = r;
            out[s * 960 + 512 + row] = r;
        }
    }
    grid_barrier();

    // ---- phase p2: 96 tiles (6 seg x 16 rowblocks), 128 rows, K=256
    for (int t = blockIdx.x; t < 96; t += gridDim.x) {
        const int s   = t >> 4;
        const int row = (t & 15) * 8 + wid;

        __syncthreads();
        if (tid < 64) sx[tid] = ((const float4*)(g_w1 + s * 256))[tid];
        __syncthreads();

        const float4* __restrict__ wv = (const float4*)(p2w + (size_t)row * 256);
        float a0 = dot4(wv[lane],      sx[lane],      0.f);
        float a1 = dot4(wv[lane + 32], sx[lane + 32], 0.f);
        float a = warp_red(a0 + a1);
        if (lane == 0) {
            float r = a + p2b[row];
            g_w2[s * 128 + row] = r;
            out[s * 960 + 768 + row] = r;
        }
    }
    grid_barrier();

    // ---- phase p3: 48 tiles (6 seg x 8 rowblocks), 64 rows, K=128
    for (int t = blockIdx.x; t < 48; t += gridDim.x) {
        const int s   = t >> 3;
        const int row = (t & 7) * 8 + wid;

        __syncthreads();
        if (tid < 32) sx[tid] = ((const float4*)(g_w2 + s * 128))[tid];
        __syncthreads();

        const float4* __restrict__ wv = (const float4*)(p3w + (size_t)row * 128);
        float a = warp_red(dot4(wv[lane], sx[lane], 0.f));
        if (lane == 0) out[s * 960 + 896 + row] = a + p3b[row];
    }
}

// ---------------- launch ----------------
extern "C" void kernel_launch(void* const* d_in, const int* in_sizes, int n_in,
                              void* d_out, int out_size)
{
    const float* xs      = (const float*)d_in[0];
    const int*   parsing = (const int*)  d_in[1];
    const float* fcA_w   = (const float*)d_in[2];
    const float* fcA_b   = (const float*)d_in[3];
    const float* fcB_w   = (const float*)d_in[4];
    const float* fcB_b   = (const float*)d_in[5];
    const float* fcC_w   = (const float*)d_in[6];
    const float* fcC_b   = (const float*)d_in[7];
    const float* p1_w    = (const float*)d_in[8];
    const float* p1_b    = (const float*)d_in[9];
    const float* p2_w    = (const float*)d_in[10];
    const float* p2_b    = (const float*)d_in[11];
    const float* p3_w    = (const float*)d_in[12];
    const float* p3_b    = (const float*)d_in[13];
    float* out = (float*)d_out;

    k_prep<<<NSEG, 512>>>(parsing);                  // #0  (mask + fm + bins)
    k_pool<<<NSEG * 128, 512>>>(xs);                 // #1
    k_fcA <<<NSEG * 256 * 4, 256>>>(fcA_w);          // #2
    k_fcBCT<<<GEMV_GRID, 256>>>(fcB_w, fcA_b, fcC_w, fcB_b, fcC_b,
                                p1_w, p1_b, p2_w, p2_b, p3_w, p3_b, out);  // #3 <- profiled
}